// round 1
// baseline (speedup 1.0000x reference)
#include <cuda_runtime.h>
#include <cuda_bf16.h>
#include <math.h>

#define B_DIM 32
#define H_DIM 56
#define W_DIM 56
#define C_DIM 256
#define NPIX (B_DIM * H_DIM * W_DIM)   // 100352
#define HW (H_DIM * W_DIM)             // 3136

// Scratch for pooled [avg, max] per pixel (no cudaMalloc allowed).
__device__ float2 g_pooled[NPIX];

// ---------------------------------------------------------------------------
// Kernel 1: channel mean + max pool. One warp per pixel.
// Each lane loads two float4 (8 channels); warp covers 256 channels = 1KB
// contiguous -> fully coalesced. Butterfly reduce sum and max together.
// ---------------------------------------------------------------------------
__global__ void __launch_bounds__(256) pool_kernel(const float* __restrict__ x) {
    int gwarp = (blockIdx.x * blockDim.x + threadIdx.x) >> 5;
    int lane  = threadIdx.x & 31;
    if (gwarp >= NPIX) return;

    const float4* __restrict__ xr = (const float4*)(x + (size_t)gwarp * C_DIM);
    float4 a = xr[lane];
    float4 b = xr[lane + 32];

    float s = (a.x + a.y) + (a.z + a.w) + (b.x + b.y) + (b.z + b.w);
    float m = fmaxf(fmaxf(fmaxf(a.x, a.y), fmaxf(a.z, a.w)),
                    fmaxf(fmaxf(b.x, b.y), fmaxf(b.z, b.w)));

    #pragma unroll
    for (int off = 16; off; off >>= 1) {
        s += __shfl_xor_sync(0xffffffffu, s, off);
        m = fmaxf(m, __shfl_xor_sync(0xffffffffu, m, off));
    }

    if (lane == 0) {
        g_pooled[gwarp] = make_float2(s * (1.0f / 256.0f), m);
    }
}

// ---------------------------------------------------------------------------
// Kernel 2: 7x7 SAME conv over pooled [avg,max] -> sigmoid -> scale x.
// One warp per pixel. Taps (49) distributed over lanes (pooled + weights are
// L2/L1-hot: pooled map is 0.8MB, weights 98 floats). Warp-reduce the conv
// sum, compute sigmoid, then every lane scales 8 channels (2x float4).
// ---------------------------------------------------------------------------
__global__ void __launch_bounds__(256) conv_scale_kernel(
    const float* __restrict__ x,
    const float* __restrict__ w,     // [7,7,2,1] HWIO -> w[(dy*7+dx)*2 + i]
    const float* __restrict__ bias,  // [1]
    float* __restrict__ out)
{
    int gwarp = (blockIdx.x * blockDim.x + threadIdx.x) >> 5;
    int lane  = threadIdx.x & 31;
    if (gwarp >= NPIX) return;

    int bb  = gwarp / HW;
    int rem = gwarp - bb * HW;
    int hy  = rem / W_DIM;
    int wx  = rem - hy * W_DIM;

    const float2* __restrict__ pooled_b = g_pooled + bb * HW;

    float acc = 0.0f;
    #pragma unroll
    for (int t = lane; t < 49; t += 32) {
        int dy = t / 7;
        int dx = t - dy * 7;
        int yy = hy + dy - 3;
        int xx = wx + dx - 3;
        if (yy >= 0 && yy < H_DIM && xx >= 0 && xx < W_DIM) {
            float2 pv = __ldg(&pooled_b[yy * W_DIM + xx]);
            float  w0 = __ldg(&w[t * 2 + 0]);
            float  w1 = __ldg(&w[t * 2 + 1]);
            acc = fmaf(pv.x, w0, acc);
            acc = fmaf(pv.y, w1, acc);
        }
    }

    #pragma unroll
    for (int off = 16; off; off >>= 1)
        acc += __shfl_xor_sync(0xffffffffu, acc, off);

    float z = acc + __ldg(bias);
    float attn = 1.0f / (1.0f + __expf(-z));
    // broadcast (all lanes have the same value after xor-reduce, but be safe)
    attn = __shfl_sync(0xffffffffu, attn, 0);

    const float4* __restrict__ xr = (const float4*)(x + (size_t)gwarp * C_DIM);
    float4* __restrict__ orow = (float4*)(out + (size_t)gwarp * C_DIM);

    float4 v0 = xr[lane];
    float4 v1 = xr[lane + 32];
    v0.x *= attn; v0.y *= attn; v0.z *= attn; v0.w *= attn;
    v1.x *= attn; v1.y *= attn; v1.z *= attn; v1.w *= attn;
    orow[lane]      = v0;
    orow[lane + 32] = v1;
}

extern "C" void kernel_launch(void* const* d_in, const int* in_sizes, int n_in,
                              void* d_out, int out_size) {
    const float* x  = (const float*)d_in[0];
    const float* w  = (const float*)d_in[1];
    const float* b  = (const float*)d_in[2];
    float* out = (float*)d_out;

    // warp per pixel, 8 warps (256 threads) per block
    const int threads = 256;
    const int warps_per_block = threads / 32;
    const int blocks = (NPIX + warps_per_block - 1) / warps_per_block;

    pool_kernel<<<blocks, threads>>>(x);
    conv_scale_kernel<<<blocks, threads>>>(x, w, b, out);
}

// round 2
// speedup vs baseline: 1.0401x; 1.0401x over previous
#include <cuda_runtime.h>
#include <cuda_bf16.h>
#include <math.h>

#define B_DIM 32
#define H_DIM 56
#define W_DIM 56
#define C_DIM 256
#define NPIX (B_DIM * H_DIM * W_DIM)   // 100352
#define HW (H_DIM * W_DIM)             // 3136

// Scratch (no cudaMalloc allowed): pooled [avg,max] and attn map per pixel.
__device__ float2 g_pooled[NPIX];
__device__ float  g_attn[NPIX];

// ---------------------------------------------------------------------------
// Kernel 1: channel mean+max pool. 2 pixels per warp, 16 lanes per pixel.
// Each lane front-batches 4 float4 loads (MLP=4), reduces in-lane, then a
// 4-step segmented butterfly across its 16-lane group.
// Per load instruction the warp reads 2 contiguous 256B chunks (coalesced).
// ---------------------------------------------------------------------------
__global__ void __launch_bounds__(256) pool_kernel(const float* __restrict__ x) {
    int warp = (blockIdx.x * blockDim.x + threadIdx.x) >> 5;
    int lane = threadIdx.x & 31;
    int sub  = lane >> 4;          // which of the warp's 2 pixels
    int co   = lane & 15;          // float4 slot within pixel
    int pix  = warp * 2 + sub;
    if (pix >= NPIX) return;

    const float4* __restrict__ xr = (const float4*)(x + (size_t)pix * C_DIM);
    float4 v0 = xr[co];
    float4 v1 = xr[co + 16];
    float4 v2 = xr[co + 32];
    float4 v3 = xr[co + 48];

    float s = ((v0.x + v0.y) + (v0.z + v0.w)) + ((v1.x + v1.y) + (v1.z + v1.w))
            + ((v2.x + v2.y) + (v2.z + v2.w)) + ((v3.x + v3.y) + (v3.z + v3.w));
    float m = fmaxf(fmaxf(fmaxf(fmaxf(v0.x, v0.y), fmaxf(v0.z, v0.w)),
                          fmaxf(fmaxf(v1.x, v1.y), fmaxf(v1.z, v1.w))),
                    fmaxf(fmaxf(fmaxf(v2.x, v2.y), fmaxf(v2.z, v2.w)),
                          fmaxf(fmaxf(v3.x, v3.y), fmaxf(v3.z, v3.w))));

    #pragma unroll
    for (int off = 8; off; off >>= 1) {
        s += __shfl_xor_sync(0xffffffffu, s, off);
        m = fmaxf(m, __shfl_xor_sync(0xffffffffu, m, off));
    }

    if (co == 0) {
        g_pooled[pix] = make_float2(s * (1.0f / 256.0f), m);
    }
}

// ---------------------------------------------------------------------------
// Kernel 2: 7x7 SAME conv over pooled map -> sigmoid -> attn map.
// 16x16 pixel tile per block, 22x22 float2 halo in smem, weights in smem.
// Only 512 blocks; everything is L2-hot (pooled map = 0.8MB).
// ---------------------------------------------------------------------------
__global__ void __launch_bounds__(256) conv_attn_kernel(
    const float* __restrict__ w,     // [7,7,2,1] HWIO
    const float* __restrict__ bias)  // [1]
{
    __shared__ float2 tile[22][22];
    __shared__ float  ws[98];
    __shared__ float  bs;

    int bb  = blockIdx.z;
    int ty0 = blockIdx.y * 16;
    int tx0 = blockIdx.x * 16;
    int tid = threadIdx.y * 16 + threadIdx.x;

    if (tid < 98) ws[tid] = w[tid];
    if (tid == 127) bs = bias[0];

    const float2* __restrict__ pooled_b = g_pooled + bb * HW;
    #pragma unroll
    for (int i = tid; i < 22 * 22; i += 256) {
        int r = i / 22;
        int c = i - r * 22;
        int yy = ty0 + r - 3;
        int xx = tx0 + c - 3;
        float2 v = make_float2(0.0f, 0.0f);
        if (yy >= 0 && yy < H_DIM && xx >= 0 && xx < W_DIM)
            v = pooled_b[yy * W_DIM + xx];
        tile[r][c] = v;
    }
    __syncthreads();

    int hy = ty0 + threadIdx.y;
    int wx = tx0 + threadIdx.x;
    if (hy < H_DIM && wx < W_DIM) {
        float acc = bs;
        #pragma unroll
        for (int dy = 0; dy < 7; dy++) {
            #pragma unroll
            for (int dx = 0; dx < 7; dx++) {
                float2 p = tile[threadIdx.y + dy][threadIdx.x + dx];
                acc = fmaf(p.x, ws[(dy * 7 + dx) * 2 + 0], acc);
                acc = fmaf(p.y, ws[(dy * 7 + dx) * 2 + 1], acc);
            }
        }
        g_attn[bb * HW + hy * W_DIM + wx] = 1.0f / (1.0f + __expf(-acc));
    }
}

// ---------------------------------------------------------------------------
// Kernel 3: pure streaming scale: out = x * attn[pixel].
// Block-strided: each thread does 4 float4 ld/st, each instruction is a
// fully-coalesced 512B warp access. attn via __ldg (L1/L2-hot, 0.4MB).
// 6272 blocks x 256 threads covers exactly NPIX*256 floats.
// ---------------------------------------------------------------------------
__global__ void __launch_bounds__(256) scale_kernel(
    const float* __restrict__ x,
    float* __restrict__ out)
{
    int base = blockIdx.x * 1024 + threadIdx.x;   // float4 index
    const float4* __restrict__ xr = (const float4*)x;
    float4* __restrict__ o = (float4*)out;

    int i0 = base;
    int i1 = base + 256;
    int i2 = base + 512;
    int i3 = base + 768;

    // front-batch all loads
    float4 v0 = xr[i0];
    float4 v1 = xr[i1];
    float4 v2 = xr[i2];
    float4 v3 = xr[i3];
    float a0 = __ldg(&g_attn[i0 >> 6]);
    float a1 = __ldg(&g_attn[i1 >> 6]);
    float a2 = __ldg(&g_attn[i2 >> 6]);
    float a3 = __ldg(&g_attn[i3 >> 6]);

    v0.x *= a0; v0.y *= a0; v0.z *= a0; v0.w *= a0;
    v1.x *= a1; v1.y *= a1; v1.z *= a1; v1.w *= a1;
    v2.x *= a2; v2.y *= a2; v2.z *= a2; v2.w *= a2;
    v3.x *= a3; v3.y *= a3; v3.z *= a3; v3.w *= a3;

    o[i0] = v0;
    o[i1] = v1;
    o[i2] = v2;
    o[i3] = v3;
}

extern "C" void kernel_launch(void* const* d_in, const int* in_sizes, int n_in,
                              void* d_out, int out_size) {
    const float* x  = (const float*)d_in[0];
    const float* w  = (const float*)d_in[1];
    const float* b  = (const float*)d_in[2];
    float* out = (float*)d_out;

    // pool: 2 pixels per warp -> NPIX/2 warps -> /8 warps per block
    const int pool_blocks = (NPIX / 2 + 7) / 8;   // 6272
    pool_kernel<<<pool_blocks, 256>>>(x);

    dim3 cgrid((W_DIM + 15) / 16, (H_DIM + 15) / 16, B_DIM);  // 4x4x32
    conv_attn_kernel<<<cgrid, dim3(16, 16)>>>(w, b);

    const int scale_blocks = (NPIX * (C_DIM / 4)) / 1024;     // 6272
    scale_kernel<<<scale_blocks, 256>>>(x, out);
}

// round 3
// speedup vs baseline: 1.1703x; 1.1252x over previous
#include <cuda_runtime.h>
#include <cuda_bf16.h>
#include <math.h>

#define B_DIM 32
#define H_DIM 56
#define W_DIM 56
#define C_DIM 256
#define NPIX (B_DIM * H_DIM * W_DIM)   // 100352
#define HW (H_DIM * W_DIM)             // 3136

// Scratch (no cudaMalloc allowed): pooled [avg,max] and attn map per pixel.
__device__ float2 g_pooled[NPIX];
__device__ float  g_attn[NPIX];

// ---------------------------------------------------------------------------
// Kernel 1: channel mean+max pool. 4 pixels per warp, 8 lanes per pixel.
// Each lane front-batches 8 float4 loads (MLP_p1=8), reduces in-lane, then a
// 3-step segmented butterfly across its 8-lane group.
// Per instruction: 4 x 128B fully-used cache lines.
// Default cache policy: we WANT x resident in L2 for the scale kernel.
// ---------------------------------------------------------------------------
__global__ void __launch_bounds__(256) pool_kernel(const float* __restrict__ x) {
    int warp = (blockIdx.x * blockDim.x + threadIdx.x) >> 5;
    int lane = threadIdx.x & 31;
    int sub  = lane >> 3;          // which of the warp's 4 pixels
    int co   = lane & 7;           // float4 slot within pixel
    int pix  = warp * 4 + sub;
    if (pix >= NPIX) return;

    const float4* __restrict__ xr = (const float4*)(x + (size_t)pix * C_DIM);
    float4 v0 = xr[co];
    float4 v1 = xr[co + 8];
    float4 v2 = xr[co + 16];
    float4 v3 = xr[co + 24];
    float4 v4 = xr[co + 32];
    float4 v5 = xr[co + 40];
    float4 v6 = xr[co + 48];
    float4 v7 = xr[co + 56];

    float s = (((v0.x + v0.y) + (v0.z + v0.w)) + ((v1.x + v1.y) + (v1.z + v1.w)))
            + (((v2.x + v2.y) + (v2.z + v2.w)) + ((v3.x + v3.y) + (v3.z + v3.w)))
            + (((v4.x + v4.y) + (v4.z + v4.w)) + ((v5.x + v5.y) + (v5.z + v5.w)))
            + (((v6.x + v6.y) + (v6.z + v6.w)) + ((v7.x + v7.y) + (v7.z + v7.w)));

    float m01 = fmaxf(fmaxf(fmaxf(v0.x, v0.y), fmaxf(v0.z, v0.w)),
                      fmaxf(fmaxf(v1.x, v1.y), fmaxf(v1.z, v1.w)));
    float m23 = fmaxf(fmaxf(fmaxf(v2.x, v2.y), fmaxf(v2.z, v2.w)),
                      fmaxf(fmaxf(v3.x, v3.y), fmaxf(v3.z, v3.w)));
    float m45 = fmaxf(fmaxf(fmaxf(v4.x, v4.y), fmaxf(v4.z, v4.w)),
                      fmaxf(fmaxf(v5.x, v5.y), fmaxf(v5.z, v5.w)));
    float m67 = fmaxf(fmaxf(fmaxf(v6.x, v6.y), fmaxf(v6.z, v6.w)),
                      fmaxf(fmaxf(v7.x, v7.y), fmaxf(v7.z, v7.w)));
    float m = fmaxf(fmaxf(m01, m23), fmaxf(m45, m67));

    #pragma unroll
    for (int off = 4; off; off >>= 1) {
        s += __shfl_xor_sync(0xffffffffu, s, off);
        m = fmaxf(m, __shfl_xor_sync(0xffffffffu, m, off));
    }

    if (co == 0) {
        g_pooled[pix] = make_float2(s * (1.0f / 256.0f), m);
    }
}

// ---------------------------------------------------------------------------
// Kernel 2: 7x7 SAME conv over pooled map -> sigmoid -> attn map.
// 16x16 pixel tile per block, 22x22 float2 halo in smem, weights in smem.
// Only 512 blocks; pooled map (0.8MB) is L2-hot.
// ---------------------------------------------------------------------------
__global__ void __launch_bounds__(256) conv_attn_kernel(
    const float* __restrict__ w,     // [7,7,2,1] HWIO
    const float* __restrict__ bias)  // [1]
{
    __shared__ float2 tile[22][22];
    __shared__ float  ws[98];
    __shared__ float  bs;

    int bb  = blockIdx.z;
    int ty0 = blockIdx.y * 16;
    int tx0 = blockIdx.x * 16;
    int tid = threadIdx.y * 16 + threadIdx.x;

    if (tid < 98) ws[tid] = w[tid];
    if (tid == 127) bs = bias[0];

    const float2* __restrict__ pooled_b = g_pooled + bb * HW;
    #pragma unroll
    for (int i = tid; i < 22 * 22; i += 256) {
        int r = i / 22;
        int c = i - r * 22;
        int yy = ty0 + r - 3;
        int xx = tx0 + c - 3;
        float2 v = make_float2(0.0f, 0.0f);
        if (yy >= 0 && yy < H_DIM && xx >= 0 && xx < W_DIM)
            v = pooled_b[yy * W_DIM + xx];
        tile[r][c] = v;
    }
    __syncthreads();

    int hy = ty0 + threadIdx.y;
    int wx = tx0 + threadIdx.x;
    if (hy < H_DIM && wx < W_DIM) {
        float acc = bs;
        #pragma unroll
        for (int dy = 0; dy < 7; dy++) {
            #pragma unroll
            for (int dx = 0; dx < 7; dx++) {
                float2 p = tile[threadIdx.y + dy][threadIdx.x + dx];
                acc = fmaf(p.x, ws[(dy * 7 + dx) * 2 + 0], acc);
                acc = fmaf(p.y, ws[(dy * 7 + dx) * 2 + 1], acc);
            }
        }
        g_attn[bb * HW + hy * W_DIM + wx] = 1.0f / (1.0f + __expf(-acc));
    }
}

// ---------------------------------------------------------------------------
// Kernel 3: pure streaming scale: out = x * attn[pixel].
// Processed in REVERSE block order: pool left x resident in L2 (103MB < 126MB)
// with the tail most-recently-used; reverse traversal consumes the resident
// tail first while LRU evictions chew the head we need last.
// x reads use __ldcs (last-use, evict-first after hit); out writes use __stcs
// (never re-read, allocate as preferred victim) to protect x residency.
// 8 float4 per thread, block-strided, fully coalesced.
// ---------------------------------------------------------------------------
__global__ void __launch_bounds__(256) scale_kernel(
    const float* __restrict__ x,
    float* __restrict__ out)
{
    // reverse block order for L2 reuse
    int blk = gridDim.x - 1 - blockIdx.x;
    int base = blk * 2048 + threadIdx.x;   // float4 index
    const float4* __restrict__ xr = (const float4*)x;
    float4* __restrict__ o = (float4*)out;

    float4 v[8];
    float  a[8];
    #pragma unroll
    for (int j = 0; j < 8; j++)
        v[j] = __ldcs(&xr[base + j * 256]);
    #pragma unroll
    for (int j = 0; j < 8; j++)
        a[j] = __ldg(&g_attn[(base + j * 256) >> 6]);

    #pragma unroll
    for (int j = 0; j < 8; j++) {
        v[j].x *= a[j]; v[j].y *= a[j]; v[j].z *= a[j]; v[j].w *= a[j];
    }

    #pragma unroll
    for (int j = 0; j < 8; j++)
        __stcs(&o[base + j * 256], v[j]);
}

extern "C" void kernel_launch(void* const* d_in, const int* in_sizes, int n_in,
                              void* d_out, int out_size) {
    const float* x  = (const float*)d_in[0];
    const float* w  = (const float*)d_in[1];
    const float* b  = (const float*)d_in[2];
    float* out = (float*)d_out;

    // pool: 4 pixels per warp -> NPIX/4 warps -> /8 warps per block
    const int pool_blocks = (NPIX / 4) / 8;       // 3136
    pool_kernel<<<pool_blocks, 256>>>(x);

    dim3 cgrid((W_DIM + 15) / 16, (H_DIM + 15) / 16, B_DIM);  // 4x4x32
    conv_attn_kernel<<<cgrid, dim3(16, 16)>>>(w, b);

    const int scale_blocks = (NPIX * (C_DIM / 4)) / 2048;     // 3136
    scale_kernel<<<scale_blocks, 256>>>(x, out);
}